// round 12
// baseline (speedup 1.0000x reference)
#include <cuda_runtime.h>
#include <cuda_fp16.h>
#include <cstdint>

// relu(X[131072,256] @ W[256,256]^T + b), fp32.
// R11: R9 pipeline shape (full-chunk prefetch cover), but BM=64 / 256 threads /
// 2 CTAs per SM — cross-CTA overlap hides per-chunk convert/wait/barrier tails.

#define KDIM 256
#define NDIM 256
#define BM   64
#define KC   64
#define NCHUNK (KDIM / KC)
#define NTHR 256

#define SM_BIAS  0
#define SM_BUF   1024
#define OFF_A    0          // 64 rows x 128B = 8KB
#define OFF_B    8192       // 256 rows x 128B = 32KB
#define BUF_BYTES 40960
#define SMEM_TOTAL (SM_BUF + 2 * BUF_BYTES)   // 82944 -> 2 CTAs/SM

__device__ __forceinline__ uint32_t smem_u32(const void* p) {
    uint32_t a;
    asm("{ .reg .u64 t; cvta.to.shared.u64 t, %1; cvt.u32.u64 %0, t; }" : "=r"(a) : "l"(p));
    return a;
}

__device__ __forceinline__ void cp_async16(uint32_t dst, const void* src) {
    asm volatile("cp.async.cg.shared.global [%0], [%1], 16;" :: "r"(dst), "l"(src) : "memory");
}
__device__ __forceinline__ void cp_commit() {
    asm volatile("cp.async.commit_group;" ::: "memory");
}
__device__ __forceinline__ void cp_wait0() {
    asm volatile("cp.async.wait_group 0;" ::: "memory");
}

__device__ __forceinline__ void ldm_x4(uint32_t addr, uint32_t& r0, uint32_t& r1,
                                       uint32_t& r2, uint32_t& r3) {
    asm volatile("ldmatrix.sync.aligned.m8n8.x4.shared.b16 {%0,%1,%2,%3}, [%4];"
                 : "=r"(r0), "=r"(r1), "=r"(r2), "=r"(r3) : "r"(addr));
}

__device__ __forceinline__ void mma16816(float* c, const uint32_t* a, uint32_t b0, uint32_t b1) {
    asm volatile(
        "mma.sync.aligned.m16n8k16.row.col.f32.f16.f16.f32 "
        "{%0,%1,%2,%3}, {%4,%5,%6,%7}, {%8,%9}, {%0,%1,%2,%3};"
        : "+f"(c[0]), "+f"(c[1]), "+f"(c[2]), "+f"(c[3])
        : "r"(a[0]), "r"(a[1]), "r"(a[2]), "r"(a[3]), "r"(b0), "r"(b1));
}

__device__ __half g_Wh[NDIM * KDIM];

__global__ void split_w_kernel(const float* __restrict__ W) {
    int i = blockIdx.x * 256 + threadIdx.x;
    g_Wh[i] = __float2half_rn(W[i]);
}

// convert one float4 (4 K values) -> fp16 and store swizzled
__device__ __forceinline__ void conv_store(float4 v, char* abuf, int row, int c) {
    __half h0 = __float2half_rn(v.x);
    __half h1 = __float2half_rn(v.y);
    __half h2 = __float2half_rn(v.z);
    __half h3 = __float2half_rn(v.w);
    uint2 hv;
    hv.x = (uint32_t)__half_as_ushort(h0) | ((uint32_t)__half_as_ushort(h1) << 16);
    hv.y = (uint32_t)__half_as_ushort(h2) | ((uint32_t)__half_as_ushort(h3) << 16);
    uint32_t off = (uint32_t)(row * 128 + c * 8);
    uint32_t swo = off ^ ((off >> 3) & 0x70);
    *(uint2*)(abuf + swo) = hv;
}

__global__ __launch_bounds__(NTHR, 2)
void gemm_hmma_kernel(const float* __restrict__ X,
                      const float* __restrict__ bias,
                      float* __restrict__ out) {
    extern __shared__ char sm[];
    const uint32_t smb = smem_u32(sm);
    const int tid  = threadIdx.x;
    const int wid  = tid >> 5;
    const int lane = tid & 31;
    const int bx   = blockIdx.x;

    const int wm = wid & 1;        // M half (32 rows)
    const int wn = wid >> 1;       // N quarter (64 cols)

    ((float*)(sm + SM_BIAS))[tid] = bias[tid];

    const float* Xblk = X + (size_t)bx * BM * KDIM;

    const uint32_t swx     = (uint32_t)(lane & 7) << 4;
    const int a_mrow       = wm * 32 + (lane & 7) + ((lane >> 3) & 1) * 8;
    const uint32_t a_khalf = (uint32_t)(lane >> 4) * 16;
    const int b_nrow       = wn * 64 + (lane & 7) + ((lane >> 4) ? 8 : 0);
    const uint32_t b_khalf = (uint32_t)((lane >> 3) & 1) * 16;

    const int xr = tid >> 4;       // 0..15 (rows xr + it*16)
    const int xc = tid & 15;

    float acc[2][8][4];
    #pragma unroll
    for (int i = 0; i < 2; i++)
        #pragma unroll
        for (int j = 0; j < 8; j++)
            #pragma unroll
            for (int q = 0; q < 4; q++) acc[i][j][q] = 0.0f;

    // ---- prologue: build chunk 0
    {
        char* abuf = sm + SM_BUF + OFF_A;
        #pragma unroll
        for (int it = 0; it < 4; it++) {
            float4 v = *(const float4*)(Xblk + (size_t)(xr + it * 16) * KDIM + xc * 4);
            conv_store(v, abuf, xr + it * 16, xc);
        }
        #pragma unroll
        for (int it = 0; it < 8; it++) {
            int id = tid + it * NTHR;
            int r = id >> 3, c = id & 7;
            uint32_t off = (uint32_t)(r * 128 + c * 16);
            uint32_t swo = off ^ ((off >> 3) & 0x70);
            cp_async16(smb + SM_BUF + OFF_B + swo, g_Wh + r * KDIM + c * 8);
        }
        cp_commit();
        cp_wait0();
        __syncthreads();
    }

    for (int kc = 0; kc < NCHUNK; kc++) {
        const uint32_t cur  = smb + SM_BUF + (uint32_t)(kc & 1) * BUF_BYTES;
        const uint32_t nxtb = smb + SM_BUF + (uint32_t)((kc & 1) ^ 1) * BUF_BYTES;
        char* nabuf = sm + (nxtb - smb) + OFF_A;
        const bool pre = (kc + 1 < NCHUNK);
        const int k0 = (kc + 1) * KC;

        float4 xv[4];

        // ---- ALL prefetch for chunk kc+1 issued up front: full-chunk cover
        if (pre) {
            #pragma unroll
            for (int it = 0; it < 4; it++)
                xv[it] = *(const float4*)(Xblk + (size_t)(xr + it * 16) * KDIM + k0 + xc * 4);
            #pragma unroll
            for (int it = 0; it < 8; it++) {
                const int id = tid + it * NTHR;
                const int r = id >> 3, c = id & 7;
                uint32_t off = (uint32_t)(r * 128 + c * 16);
                uint32_t swo = off ^ ((off >> 3) & 0x70);
                cp_async16(nxtb + OFF_B + swo, g_Wh + r * KDIM + k0 + c * 8);
            }
            cp_commit();
        }

        // ---- clean MMA loop
        #pragma unroll
        for (int kk = 0; kk < 4; kk++) {
            const uint32_t kof  = (uint32_t)(kk * 32);
            const uint32_t dynA = (kof + a_khalf) ^ swx;
            const uint32_t dynB = (kof + b_khalf) ^ swx;
            const uint32_t aB = cur + OFF_A + (uint32_t)(a_mrow * 128) + dynA;
            const uint32_t bB = cur + OFF_B + (uint32_t)(b_nrow * 128) + dynB;

            uint32_t ah[2][4];
            ldm_x4(aB,        ah[0][0], ah[0][1], ah[0][2], ah[0][3]);
            ldm_x4(aB + 2048, ah[1][0], ah[1][1], ah[1][2], ah[1][3]);

            uint32_t bh[2][4];
            ldm_x4(bB, bh[0][0], bh[0][1], bh[0][2], bh[0][3]);

            #pragma unroll
            for (int ng = 0; ng < 4; ng++) {
                const int cb = ng & 1;
                if (ng < 3) {
                    const int nb = cb ^ 1;
                    ldm_x4(bB + (uint32_t)((ng + 1) * 2048),
                           bh[nb][0], bh[nb][1], bh[nb][2], bh[nb][3]);
                }
                mma16816(acc[0][2 * ng + 0], ah[0], bh[cb][0], bh[cb][1]);
                mma16816(acc[0][2 * ng + 1], ah[0], bh[cb][2], bh[cb][3]);
                mma16816(acc[1][2 * ng + 0], ah[1], bh[cb][0], bh[cb][1]);
                mma16816(acc[1][2 * ng + 1], ah[1], bh[cb][2], bh[cb][3]);
            }
        }

        // ---- chunk end: convert X (data long since arrived), wait B, barrier
        if (pre) {
            conv_store(xv[0], nabuf, xr,      xc);
            conv_store(xv[1], nabuf, xr + 16, xc);
            conv_store(xv[2], nabuf, xr + 32, xc);
            conv_store(xv[3], nabuf, xr + 48, xc);
            cp_wait0();
        }
        __syncthreads();
    }

    // ---- epilogue: bias + relu
    const float* sb = (const float*)(sm + SM_BIAS);
    const int mbase = bx * BM + wm * 32 + (lane >> 2);
    const int nbase = wn * 64 + (lane & 3) * 2;

    #pragma unroll
    for (int mb = 0; mb < 2; mb++) {
        #pragma unroll
        for (int nb = 0; nb < 8; nb++) {
            const int n = nbase + nb * 8;
            const float b0 = sb[n], b1 = sb[n + 1];
            const int m0 = mbase + mb * 16;
            float2 v0, v1;
            v0.x = fmaxf(acc[mb][nb][0] + b0, 0.0f);
            v0.y = fmaxf(acc[mb][nb][1] + b1, 0.0f);
            v1.x = fmaxf(acc[mb][nb][2] + b0, 0.0f);
            v1.y = fmaxf(acc[mb][nb][3] + b1, 0.0f);
            *(float2*)(out + (size_t)m0 * NDIM + n) = v0;
            *(float2*)(out + (size_t)(m0 + 8) * NDIM + n) = v1;
        }
    }
}

extern "C" void kernel_launch(void* const* d_in, const int* in_sizes, int n_in,
                              void* d_out, int out_size) {
    const float* X    = (const float*)d_in[0];
    const float* W    = (const float*)d_in[1];
    const float* bias = (const float*)d_in[2];
    float* out = (float*)d_out;

    cudaFuncSetAttribute(gemm_hmma_kernel,
                         cudaFuncAttributeMaxDynamicSharedMemorySize, SMEM_TOTAL);

    split_w_kernel<<<(NDIM * KDIM) / 256, 256>>>(W);

    const int Brows = in_sizes[0] / KDIM;
    gemm_hmma_kernel<<<Brows / BM, NTHR, SMEM_TOTAL>>>(X, bias, out);
}

// round 13
// speedup vs baseline: 1.2912x; 1.2912x over previous
#include <cuda_runtime.h>
#include <cuda_fp16.h>
#include <cstdint>

// relu(X[131072,256] @ W[256,256]^T + b), fp32.
// R12: R9 skeleton (BM=128, 512thr, full-cover prefetch) with KC=128/NCHUNK=2:
// one mid-kernel tail instead of three, 8-kk MMA runs covering each prefetch.

#define KDIM 256
#define NDIM 256
#define BM   128
#define KC   128
#define NCHUNK (KDIM / KC)   // 2
#define NTHR 512

#define SM_BIAS  0
#define SM_BUF   1024
#define OFF_A    0           // 2 sub-chunks of [128 x 128B] = 32KB
#define OFF_B    32768       // 2 sub-chunks of [256 x 128B] = 64KB
#define BUF_BYTES 98304      // 96KB per stage
#define SMEM_TOTAL (SM_BUF + 2 * BUF_BYTES)   // 197632

__device__ __forceinline__ uint32_t smem_u32(const void* p) {
    uint32_t a;
    asm("{ .reg .u64 t; cvta.to.shared.u64 t, %1; cvt.u32.u64 %0, t; }" : "=r"(a) : "l"(p));
    return a;
}

__device__ __forceinline__ void cp_async16(uint32_t dst, const void* src) {
    asm volatile("cp.async.cg.shared.global [%0], [%1], 16;" :: "r"(dst), "l"(src) : "memory");
}
__device__ __forceinline__ void cp_commit() {
    asm volatile("cp.async.commit_group;" ::: "memory");
}
__device__ __forceinline__ void cp_wait0() {
    asm volatile("cp.async.wait_group 0;" ::: "memory");
}

__device__ __forceinline__ void ldm_x4(uint32_t addr, uint32_t& r0, uint32_t& r1,
                                       uint32_t& r2, uint32_t& r3) {
    asm volatile("ldmatrix.sync.aligned.m8n8.x4.shared.b16 {%0,%1,%2,%3}, [%4];"
                 : "=r"(r0), "=r"(r1), "=r"(r2), "=r"(r3) : "r"(addr));
}

__device__ __forceinline__ void mma16816(float* c, const uint32_t* a, uint32_t b0, uint32_t b1) {
    asm volatile(
        "mma.sync.aligned.m16n8k16.row.col.f32.f16.f16.f32 "
        "{%0,%1,%2,%3}, {%4,%5,%6,%7}, {%8,%9}, {%0,%1,%2,%3};"
        : "+f"(c[0]), "+f"(c[1]), "+f"(c[2]), "+f"(c[3])
        : "r"(a[0]), "r"(a[1]), "r"(a[2]), "r"(a[3]), "r"(b0), "r"(b1));
}

__device__ __half g_Wh[NDIM * KDIM];

__global__ void split_w_kernel(const float* __restrict__ W) {
    int i = blockIdx.x * 256 + threadIdx.x;
    g_Wh[i] = __float2half_rn(W[i]);
}

// convert one float4 (4 K values) -> fp16 and store swizzled into 128B-row tile
__device__ __forceinline__ void conv_store(float4 v, char* tile, int row, int c) {
    __half h0 = __float2half_rn(v.x);
    __half h1 = __float2half_rn(v.y);
    __half h2 = __float2half_rn(v.z);
    __half h3 = __float2half_rn(v.w);
    uint2 hv;
    hv.x = (uint32_t)__half_as_ushort(h0) | ((uint32_t)__half_as_ushort(h1) << 16);
    hv.y = (uint32_t)__half_as_ushort(h2) | ((uint32_t)__half_as_ushort(h3) << 16);
    uint32_t off = (uint32_t)(row * 128 + c * 8);
    uint32_t swo = off ^ ((off >> 3) & 0x70);
    *(uint2*)(tile + swo) = hv;
}

__global__ __launch_bounds__(NTHR, 1)
void gemm_hmma_kernel(const float* __restrict__ X,
                      const float* __restrict__ bias,
                      float* __restrict__ out) {
    extern __shared__ char sm[];
    const uint32_t smb = smem_u32(sm);
    const int tid  = threadIdx.x;
    const int wid  = tid >> 5;
    const int lane = tid & 31;
    const int bx   = blockIdx.x;

    const int wm = wid & 3;        // M quarter (32 rows)
    const int wn = wid >> 2;       // N quarter (64 cols)

    if (tid < 256) ((float*)(sm + SM_BIAS))[tid] = bias[tid];

    const float* Xblk = X + (size_t)bx * BM * KDIM;

    const uint32_t swx     = (uint32_t)(lane & 7) << 4;
    const int a_mrow       = wm * 32 + (lane & 7) + ((lane >> 3) & 1) * 8;
    const uint32_t a_khalf = (uint32_t)(lane >> 4) * 16;
    const int b_nrow       = wn * 64 + (lane & 7) + ((lane >> 4) ? 8 : 0);
    const uint32_t b_khalf = (uint32_t)((lane >> 3) & 1) * 16;

    const int xr = tid >> 4;       // 0..31; rows xr + 32*it
    const int xc = tid & 15;       // float4 slot within 64-K half

    float acc[2][8][4];
    #pragma unroll
    for (int i = 0; i < 2; i++)
        #pragma unroll
        for (int j = 0; j < 8; j++)
            #pragma unroll
            for (int q = 0; q < 4; q++) acc[i][j][q] = 0.0f;

    // ---- prologue: build chunk 0 (K 0..127)
    {
        char* abuf = sm + SM_BUF + OFF_A;
        #pragma unroll
        for (int it = 0; it < 4; it++) {
            float4 v = *(const float4*)(Xblk + (size_t)(xr + it * 32) * KDIM + xc * 4);
            conv_store(v, abuf, xr + it * 32, xc);                 // K 0..63 -> sub0
        }
        #pragma unroll
        for (int it = 0; it < 4; it++) {
            float4 v = *(const float4*)(Xblk + (size_t)(xr + it * 32) * KDIM + 64 + xc * 4);
            conv_store(v, abuf + 16384, xr + it * 32, xc);         // K 64..127 -> sub1
        }
        #pragma unroll
        for (int it = 0; it < 8; it++) {
            int id = tid + it * NTHR;          // 0..4095
            int r  = id >> 4;                  // W row 0..255
            int ks = id & 15;                  // 16B slot within 256B row
            int kch = ks >> 3, c = ks & 7;
            uint32_t off = (uint32_t)(r * 128 + c * 16);
            uint32_t swo = off ^ ((off >> 3) & 0x70);
            cp_async16(smb + SM_BUF + OFF_B + (uint32_t)(kch * 32768) + swo,
                       g_Wh + r * KDIM + ks * 8);
        }
        cp_commit();
        cp_wait0();
        __syncthreads();
    }

    #pragma unroll
    for (int kc = 0; kc < NCHUNK; kc++) {
        const uint32_t cur  = smb + SM_BUF + (uint32_t)(kc & 1) * BUF_BYTES;
        const uint32_t nxtb = smb + SM_BUF + (uint32_t)((kc & 1) ^ 1) * BUF_BYTES;
        char* nabuf = sm + (nxtb - smb) + OFF_A;
        const bool pre = (kc + 1 < NCHUNK);
        const int k0 = (kc + 1) * KC;          // 128

        float4 xv[4];

        // ---- prefetch for chunk kc+1: X batch 1 + all B, issued up front
        if (pre) {
            #pragma unroll
            for (int it = 0; it < 4; it++)
                xv[it] = *(const float4*)(Xblk + (size_t)(xr + it * 32) * KDIM + k0 + xc * 4);
            #pragma unroll
            for (int it = 0; it < 8; it++) {
                const int id = tid + it * NTHR;
                const int r  = id >> 4;
                const int ks = id & 15;
                const int kch = ks >> 3, c = ks & 7;
                uint32_t off = (uint32_t)(r * 128 + c * 16);
                uint32_t swo = off ^ ((off >> 3) & 0x70);
                cp_async16(nxtb + OFF_B + (uint32_t)(kch * 32768) + swo,
                           g_Wh + r * KDIM + k0 + ks * 8);
            }
            cp_commit();
        }

        // ---- MMA loop: 8 kk steps
        #pragma unroll
        for (int kk = 0; kk < 8; kk++) {
            const uint32_t subA = (uint32_t)((kk >> 2) * 16384);
            const uint32_t subB = (uint32_t)((kk >> 2) * 32768);
            const uint32_t kof  = (uint32_t)((kk & 3) * 32);
            const uint32_t dynA = (kof + a_khalf) ^ swx;
            const uint32_t dynB = (kof + b_khalf) ^ swx;
            const uint32_t aB = cur + OFF_A + subA + (uint32_t)(a_mrow * 128) + dynA;
            const uint32_t bB = cur + OFF_B + subB + (uint32_t)(b_nrow * 128) + dynB;

            uint32_t ah[2][4];
            ldm_x4(aB,        ah[0][0], ah[0][1], ah[0][2], ah[0][3]);
            ldm_x4(aB + 2048, ah[1][0], ah[1][1], ah[1][2], ah[1][3]);

            uint32_t bh[2][4];
            ldm_x4(bB, bh[0][0], bh[0][1], bh[0][2], bh[0][3]);

            #pragma unroll
            for (int ng = 0; ng < 4; ng++) {
                const int cb = ng & 1;
                if (ng < 3) {
                    const int nb = cb ^ 1;
                    ldm_x4(bB + (uint32_t)((ng + 1) * 2048),
                           bh[nb][0], bh[nb][1], bh[nb][2], bh[nb][3]);
                }
                mma16816(acc[0][2 * ng + 0], ah[0], bh[cb][0], bh[cb][1]);
                mma16816(acc[0][2 * ng + 1], ah[0], bh[cb][2], bh[cb][3]);
                mma16816(acc[1][2 * ng + 0], ah[1], bh[cb][0], bh[cb][1]);
                mma16816(acc[1][2 * ng + 1], ah[1], bh[cb][2], bh[cb][3]);
            }

            // batch-1 convert (cover: 3 kk ~ 750cyc), then batch-2 LDG
            if (pre && kk == 3) {
                conv_store(xv[0], nabuf, xr,      xc);
                conv_store(xv[1], nabuf, xr + 32, xc);
                conv_store(xv[2], nabuf, xr + 64, xc);
                conv_store(xv[3], nabuf, xr + 96, xc);
            }
            if (pre && kk == 4) {
                #pragma unroll
                for (int it = 0; it < 4; it++)
                    xv[it] = *(const float4*)(Xblk + (size_t)(xr + it * 32) * KDIM
                                              + k0 + 64 + xc * 4);
            }
        }

        // ---- chunk tail: convert batch 2, wait B, single barrier
        if (pre) {
            conv_store(xv[0], nabuf + 16384, xr,      xc);
            conv_store(xv[1], nabuf + 16384, xr + 32, xc);
            conv_store(xv[2], nabuf + 16384, xr + 64, xc);
            conv_store(xv[3], nabuf + 16384, xr + 96, xc);
            cp_wait0();
            __syncthreads();
        }
    }

    // ---- epilogue: bias + relu
    const float* sb = (const float*)(sm + SM_BIAS);
    const int mbase = bx * BM + wm * 32 + (lane >> 2);
    const int nbase = wn * 64 + (lane & 3) * 2;

    #pragma unroll
    for (int mb = 0; mb < 2; mb++) {
        #pragma unroll
        for (int nb = 0; nb < 8; nb++) {
            const int n = nbase + nb * 8;
            const float b0 = sb[n], b1 = sb[n + 1];
            const int m0 = mbase + mb * 16;
            float2 v0, v1;
            v0.x = fmaxf(acc[mb][nb][0] + b0, 0.0f);
            v0.y = fmaxf(acc[mb][nb][1] + b1, 0.0f);
            v1.x = fmaxf(acc[mb][nb][2] + b0, 0.0f);
            v1.y = fmaxf(acc[mb][nb][3] + b1, 0.0f);
            *(float2*)(out + (size_t)m0 * NDIM + n) = v0;
            *(float2*)(out + (size_t)(m0 + 8) * NDIM + n) = v1;
        }
    }
}

extern "C" void kernel_launch(void* const* d_in, const int* in_sizes, int n_in,
                              void* d_out, int out_size) {
    const float* X    = (const float*)d_in[0];
    const float* W    = (const float*)d_in[1];
    const float* bias = (const float*)d_in[2];
    float* out = (float*)d_out;

    cudaFuncSetAttribute(gemm_hmma_kernel,
                         cudaFuncAttributeMaxDynamicSharedMemorySize, SMEM_TOTAL);

    split_w_kernel<<<(NDIM * KDIM) / 256, 256>>>(W);

    const int Brows = in_sizes[0] / KDIM;
    gemm_hmma_kernel<<<Brows / BM, NTHR, SMEM_TOTAL>>>(X, bias, out);
}

// round 14
// speedup vs baseline: 1.3589x; 1.0524x over previous
#include <cuda_runtime.h>
#include <cuda_fp16.h>
#include <cstdint>

// relu(X[131072,256] @ W[256,256]^T + b), fp32.
// R13: R9 skeleton + intra-chunk cross-kk fragment pipelining (A(kk+1)@ng1,
// B0(kk+1)@ng3) + converts spread into kk1/kk2 bodies. Tail = wait + barrier.

#define KDIM 256
#define NDIM 256
#define BM   128
#define KC   64
#define NCHUNK (KDIM / KC)
#define NTHR 512

#define SM_BIAS  0
#define SM_BUF   1024
#define OFF_A    0          // 128 rows x 128B = 16KB
#define OFF_B    16384      // 256 rows x 128B = 32KB
#define BUF_BYTES 49152
#define SMEM_TOTAL (SM_BUF + 2 * BUF_BYTES)   // 99328

__device__ __forceinline__ uint32_t smem_u32(const void* p) {
    uint32_t a;
    asm("{ .reg .u64 t; cvta.to.shared.u64 t, %1; cvt.u32.u64 %0, t; }" : "=r"(a) : "l"(p));
    return a;
}

__device__ __forceinline__ void cp_async16(uint32_t dst, const void* src) {
    asm volatile("cp.async.cg.shared.global [%0], [%1], 16;" :: "r"(dst), "l"(src) : "memory");
}
__device__ __forceinline__ void cp_commit() {
    asm volatile("cp.async.commit_group;" ::: "memory");
}
__device__ __forceinline__ void cp_wait0() {
    asm volatile("cp.async.wait_group 0;" ::: "memory");
}

__device__ __forceinline__ void ldm_x4(uint32_t addr, uint32_t* r) {
    asm volatile("ldmatrix.sync.aligned.m8n8.x4.shared.b16 {%0,%1,%2,%3}, [%4];"
                 : "=r"(r[0]), "=r"(r[1]), "=r"(r[2]), "=r"(r[3]) : "r"(addr));
}

__device__ __forceinline__ void mma16816(float* c, const uint32_t* a, uint32_t b0, uint32_t b1) {
    asm volatile(
        "mma.sync.aligned.m16n8k16.row.col.f32.f16.f16.f32 "
        "{%0,%1,%2,%3}, {%4,%5,%6,%7}, {%8,%9}, {%0,%1,%2,%3};"
        : "+f"(c[0]), "+f"(c[1]), "+f"(c[2]), "+f"(c[3])
        : "r"(a[0]), "r"(a[1]), "r"(a[2]), "r"(a[3]), "r"(b0), "r"(b1));
}

__device__ __half g_Wh[NDIM * KDIM];

__global__ void split_w_kernel(const float* __restrict__ W) {
    int i = blockIdx.x * 256 + threadIdx.x;
    g_Wh[i] = __float2half_rn(W[i]);
}

// convert one float4 (4 K values) -> fp16 and store swizzled
__device__ __forceinline__ void conv_store(float4 v, char* abuf, int row, int c) {
    __half h0 = __float2half_rn(v.x);
    __half h1 = __float2half_rn(v.y);
    __half h2 = __float2half_rn(v.z);
    __half h3 = __float2half_rn(v.w);
    uint2 hv;
    hv.x = (uint32_t)__half_as_ushort(h0) | ((uint32_t)__half_as_ushort(h1) << 16);
    hv.y = (uint32_t)__half_as_ushort(h2) | ((uint32_t)__half_as_ushort(h3) << 16);
    uint32_t off = (uint32_t)(row * 128 + c * 8);
    uint32_t swo = off ^ ((off >> 3) & 0x70);
    *(uint2*)(abuf + swo) = hv;
}

__global__ __launch_bounds__(NTHR, 1)
void gemm_hmma_kernel(const float* __restrict__ X,
                      const float* __restrict__ bias,
                      float* __restrict__ out) {
    extern __shared__ char sm[];
    const uint32_t smb = smem_u32(sm);
    const int tid  = threadIdx.x;
    const int wid  = tid >> 5;
    const int lane = tid & 31;
    const int bx   = blockIdx.x;

    const int wm = wid & 3;        // M quarter (32 rows)
    const int wn = wid >> 2;       // N quarter (64 cols)

    if (tid < 256) ((float*)(sm + SM_BIAS))[tid] = bias[tid];

    const float* Xblk = X + (size_t)bx * BM * KDIM;

    const uint32_t swx     = (uint32_t)(lane & 7) << 4;
    const int a_mrow       = wm * 32 + (lane & 7) + ((lane >> 3) & 1) * 8;
    const uint32_t a_khalf = (uint32_t)(lane >> 4) * 16;
    const int b_nrow       = wn * 64 + (lane & 7) + ((lane >> 4) ? 8 : 0);
    const uint32_t b_khalf = (uint32_t)((lane >> 3) & 1) * 16;

    const int xr = tid >> 4;
    const int xc = tid & 15;

    float acc[2][8][4];
    #pragma unroll
    for (int i = 0; i < 2; i++)
        #pragma unroll
        for (int j = 0; j < 8; j++)
            #pragma unroll
            for (int q = 0; q < 4; q++) acc[i][j][q] = 0.0f;

    // ---- prologue: build chunk 0
    {
        char* abuf = sm + SM_BUF + OFF_A;
        #pragma unroll
        for (int it = 0; it < 4; it++) {
            float4 v = *(const float4*)(Xblk + (size_t)(xr + it * 32) * KDIM + xc * 4);
            conv_store(v, abuf, xr + it * 32, xc);
        }
        #pragma unroll
        for (int it = 0; it < 4; it++) {
            int id = tid + it * NTHR;
            int r = id >> 3, c = id & 7;
            uint32_t off = (uint32_t)(r * 128 + c * 16);
            uint32_t swo = off ^ ((off >> 3) & 0x70);
            cp_async16(smb + SM_BUF + OFF_B + swo, g_Wh + r * KDIM + c * 8);
        }
        cp_commit();
        cp_wait0();
        __syncthreads();
    }

    for (int kc = 0; kc < NCHUNK; kc++) {
        const uint32_t cur  = smb + SM_BUF + (uint32_t)(kc & 1) * BUF_BYTES;
        const uint32_t nxtb = smb + SM_BUF + (uint32_t)((kc & 1) ^ 1) * BUF_BYTES;
        char* nabuf = sm + (nxtb - smb) + OFF_A;
        const bool pre = (kc + 1 < NCHUNK);
        const int k0 = (kc + 1) * KC;

        float4 xv[4];

        // ---- ALL prefetch for chunk kc+1 issued up front: full-chunk cover
        if (pre) {
            #pragma unroll
            for (int it = 0; it < 4; it++)
                xv[it] = *(const float4*)(Xblk + (size_t)(xr + it * 32) * KDIM + k0 + xc * 4);
            #pragma unroll
            for (int it = 0; it < 4; it++) {
                const int id = tid + it * NTHR;
                const int r = id >> 3, c = id & 7;
                uint32_t off = (uint32_t)(r * 128 + c * 16);
                uint32_t swo = off ^ ((off >> 3) & 0x70);
                cp_async16(nxtb + OFF_B + swo, g_Wh + r * KDIM + k0 + c * 8);
            }
            cp_commit();
        }

        // ---- frag-pipelined MMA loop
        const uint32_t aCol = cur + OFF_A + (uint32_t)(a_mrow * 128);
        const uint32_t bCol = cur + OFF_B + (uint32_t)(b_nrow * 128);
        #define A_ADDR(kk) (aCol + (((uint32_t)(kk) * 32 + a_khalf) ^ swx))
        #define B_ADDR(kk, ng) (bCol + (uint32_t)((ng) * 2048) + (((uint32_t)(kk) * 32 + b_khalf) ^ swx))

        uint32_t ah[2][2][4];
        uint32_t bh[2][4];

        ldm_x4(A_ADDR(0),        ah[0][0]);
        ldm_x4(A_ADDR(0) + 2048, ah[0][1]);
        ldm_x4(B_ADDR(0, 0),     bh[0]);

        #pragma unroll
        for (int kk = 0; kk < 4; kk++) {
            const int kb = kk & 1;
            #pragma unroll
            for (int ng = 0; ng < 4; ng++) {
                const int cb = ng & 1;
                if (ng < 3) {
                    ldm_x4(B_ADDR(kk, ng + 1), bh[cb ^ 1]);
                } else if (kk < 3) {
                    ldm_x4(B_ADDR(kk + 1, 0), bh[0]);      // bh[0] free after ng=2
                }
                if (ng == 1 && kk < 3) {
                    ldm_x4(A_ADDR(kk + 1),        ah[kb ^ 1][0]);
                    ldm_x4(A_ADDR(kk + 1) + 2048, ah[kb ^ 1][1]);
                }
                mma16816(acc[0][2 * ng + 0], ah[kb][0], bh[cb][0], bh[cb][1]);
                mma16816(acc[0][2 * ng + 1], ah[kb][0], bh[cb][2], bh[cb][3]);
                mma16816(acc[1][2 * ng + 0], ah[kb][1], bh[cb][0], bh[cb][1]);
                mma16816(acc[1][2 * ng + 1], ah[kb][1], bh[cb][2], bh[cb][3]);
            }
            // spread converts: 2 at end of kk1, 2 at end of kk2 (other warps
            // keep the tensor pipe fed while this warp converts)
            if (pre && kk == 1) {
                conv_store(xv[0], nabuf, xr,      xc);
                conv_store(xv[1], nabuf, xr + 32, xc);
            }
            if (pre && kk == 2) {
                conv_store(xv[2], nabuf, xr + 64, xc);
                conv_store(xv[3], nabuf, xr + 96, xc);
            }
        }
        #undef A_ADDR
        #undef B_ADDR

        // ---- minimal chunk tail
        if (pre) cp_wait0();
        __syncthreads();
    }

    // ---- epilogue: bias + relu
    const float* sb = (const float*)(sm + SM_BIAS);
    const int mbase = bx * BM + wm * 32 + (lane >> 2);
    const int nbase = wn * 64 + (lane & 3) * 2;

    #pragma unroll
    for (int mb = 0; mb < 2; mb++) {
        #pragma unroll
        for (int nb = 0; nb < 8; nb++) {
            const int n = nbase + nb * 8;
            const float b0 = sb[n], b1 = sb[n + 1];
            const int m0 = mbase + mb * 16;
            float2 v0, v1;
            v0.x = fmaxf(acc[mb][nb][0] + b0, 0.0f);
            v0.y = fmaxf(acc[mb][nb][1] + b1, 0.0f);
            v1.x = fmaxf(acc[mb][nb][2] + b0, 0.0f);
            v1.y = fmaxf(acc[mb][nb][3] + b1, 0.0f);
            *(float2*)(out + (size_t)m0 * NDIM + n) = v0;
            *(float2*)(out + (size_t)(m0 + 8) * NDIM + n) = v1;
        }
    }
}

extern "C" void kernel_launch(void* const* d_in, const int* in_sizes, int n_in,
                              void* d_out, int out_size) {
    const float* X    = (const float*)d_in[0];
    const float* W    = (const float*)d_in[1];
    const float* bias = (const float*)d_in[2];
    float* out = (float*)d_out;

    cudaFuncSetAttribute(gemm_hmma_kernel,
                         cudaFuncAttributeMaxDynamicSharedMemorySize, SMEM_TOTAL);

    split_w_kernel<<<(NDIM * KDIM) / 256, 256>>>(W);

    const int Brows = in_sizes[0] / KDIM;
    gemm_hmma_kernel<<<Brows / BM, NTHR, SMEM_TOTAL>>>(X, bias, out);
}

// round 15
// speedup vs baseline: 1.4953x; 1.1003x over previous
#include <cuda_runtime.h>
#include <cuda_fp16.h>
#include <cstdint>

// relu(X[131072,256] @ W[256,256]^T + b), fp32.
// R14: persistent kernel (grid=148). W fp16 (128KB) resident in smem for the
// whole kernel; each CTA loops M-tiles with cross-tile X prefetch (R12 batch
// schedule). No per-tile W loads, no wave transitions, 2 barriers/tile.

#define KDIM 256
#define NDIM 256
#define BM   128
#define NTHR 512
#define GRID 148

#define SM_BIAS  0
#define SM_W     1024                    // 4 subs of [256 x 128B] = 128KB
#define SM_A     (1024 + 131072)         // 2 bufs x (2 subs of [128 x 128B]) = 64KB
#define SMEM_TOTAL (SM_A + 65536)        // 197632

__device__ __forceinline__ uint32_t smem_u32(const void* p) {
    uint32_t a;
    asm("{ .reg .u64 t; cvta.to.shared.u64 t, %1; cvt.u32.u64 %0, t; }" : "=r"(a) : "l"(p));
    return a;
}

__device__ __forceinline__ void cp_async16(uint32_t dst, const void* src) {
    asm volatile("cp.async.cg.shared.global [%0], [%1], 16;" :: "r"(dst), "l"(src) : "memory");
}
__device__ __forceinline__ void cp_commit() {
    asm volatile("cp.async.commit_group;" ::: "memory");
}
__device__ __forceinline__ void cp_wait0() {
    asm volatile("cp.async.wait_group 0;" ::: "memory");
}

__device__ __forceinline__ void ldm_x4(uint32_t addr, uint32_t& r0, uint32_t& r1,
                                       uint32_t& r2, uint32_t& r3) {
    asm volatile("ldmatrix.sync.aligned.m8n8.x4.shared.b16 {%0,%1,%2,%3}, [%4];"
                 : "=r"(r0), "=r"(r1), "=r"(r2), "=r"(r3) : "r"(addr));
}

__device__ __forceinline__ void mma16816(float* c, const uint32_t* a, uint32_t b0, uint32_t b1) {
    asm volatile(
        "mma.sync.aligned.m16n8k16.row.col.f32.f16.f16.f32 "
        "{%0,%1,%2,%3}, {%4,%5,%6,%7}, {%8,%9}, {%0,%1,%2,%3};"
        : "+f"(c[0]), "+f"(c[1]), "+f"(c[2]), "+f"(c[3])
        : "r"(a[0]), "r"(a[1]), "r"(a[2]), "r"(a[3]), "r"(b0), "r"(b1));
}

__device__ __half g_Wh[NDIM * KDIM];

__global__ void split_w_kernel(const float* __restrict__ W) {
    int i = blockIdx.x * 256 + threadIdx.x;
    g_Wh[i] = __float2half_rn(W[i]);
}

// convert one float4 (4 K values) -> fp16 and store swizzled into 128B-row tile
__device__ __forceinline__ void conv_store(float4 v, char* tile, int row, int c) {
    __half h0 = __float2half_rn(v.x);
    __half h1 = __float2half_rn(v.y);
    __half h2 = __float2half_rn(v.z);
    __half h3 = __float2half_rn(v.w);
    uint2 hv;
    hv.x = (uint32_t)__half_as_ushort(h0) | ((uint32_t)__half_as_ushort(h1) << 16);
    hv.y = (uint32_t)__half_as_ushort(h2) | ((uint32_t)__half_as_ushort(h3) << 16);
    uint32_t off = (uint32_t)(row * 128 + c * 8);
    uint32_t swo = off ^ ((off >> 3) & 0x70);
    *(uint2*)(tile + swo) = hv;
}

__global__ __launch_bounds__(NTHR, 1)
void gemm_hmma_kernel(const float* __restrict__ X,
                      const float* __restrict__ bias,
                      float* __restrict__ out,
                      int ntile) {
    extern __shared__ char sm[];
    const uint32_t smb = smem_u32(sm);
    const int tid  = threadIdx.x;
    const int wid  = tid >> 5;
    const int lane = tid & 31;
    const int bx   = blockIdx.x;

    const int wm = wid & 3;        // M quarter (32 rows)
    const int wn = wid >> 2;       // N quarter (64 cols)

    if (tid < 256) ((float*)(sm + SM_BIAS))[tid] = bias[tid];

    const uint32_t swx     = (uint32_t)(lane & 7) << 4;
    const int a_mrow       = wm * 32 + (lane & 7) + ((lane >> 3) & 1) * 8;
    const uint32_t a_khalf = (uint32_t)(lane >> 4) * 16;
    const int b_nrow       = wn * 64 + (lane & 7) + ((lane >> 4) ? 8 : 0);
    const uint32_t b_khalf = (uint32_t)((lane >> 3) & 1) * 16;

    const int xr = tid >> 4;       // 0..31; rows xr + 32*it
    const int xc = tid & 15;       // float4 slot within 64-K half

    float acc[2][8][4];
    #pragma unroll
    for (int i = 0; i < 2; i++)
        #pragma unroll
        for (int j = 0; j < 8; j++)
            #pragma unroll
            for (int q = 0; q < 4; q++) acc[i][j][q] = 0.0f;

    // ---- prologue (once): all of W via cp.async; X(tile bx, chunk 0) -> buf0
    #pragma unroll
    for (int it = 0; it < 16; it++) {
        int id = tid + it * NTHR;          // 0..8191 (16B units of W)
        int r  = id >> 5;                  // W row 0..255
        int ks = id & 31;                  // 16B slot within 512B row
        int kch = ks >> 3, c = ks & 7;
        uint32_t off = (uint32_t)(r * 128 + c * 16);
        uint32_t swo = off ^ ((off >> 3) & 0x70);
        cp_async16(smb + SM_W + (uint32_t)(kch * 32768) + swo, g_Wh + r * KDIM + ks * 8);
    }
    cp_commit();
    {
        const float* Xb = X + (size_t)bx * BM * KDIM;
        char* ab = sm + SM_A;
        #pragma unroll
        for (int it = 0; it < 4; it++) {
            float4 v = *(const float4*)(Xb + (size_t)(xr + it * 32) * KDIM + xc * 4);
            conv_store(v, ab, xr + it * 32, xc);                   // K 0..63 -> sub0
        }
        #pragma unroll
        for (int it = 0; it < 4; it++) {
            float4 v = *(const float4*)(Xb + (size_t)(xr + it * 32) * KDIM + 64 + xc * 4);
            conv_store(v, ab + 16384, xr + it * 32, xc);           // K 64..127 -> sub1
        }
    }
    cp_wait0();
    __syncthreads();

    int buf = 0;
    const float* sb = (const float*)(sm + SM_BIAS);

    for (int m = bx; m < ntile; m += GRID) {
        const float* Xb = X + (size_t)m * BM * KDIM;

        #pragma unroll
        for (int kc = 0; kc < 2; kc++) {
            const uint32_t curA = smb + SM_A + (uint32_t)(buf * 32768);
            char* nab = sm + SM_A + ((buf ^ 1) * 32768);
            const bool pre = (kc == 0) || (m + GRID < ntile);
            const float* Xn = (kc == 0) ? Xb : X + (size_t)(m + GRID) * BM * KDIM;
            const int kof0 = (kc == 0) ? 128 : 0;

            float4 xv[4];

            // prefetch batch 1 of next chunk's X (full-chunk LDG cover)
            if (pre) {
                #pragma unroll
                for (int it = 0; it < 4; it++)
                    xv[it] = *(const float4*)(Xn + (size_t)(xr + it * 32) * KDIM + kof0 + xc * 4);
            }

            // ---- MMA loop: 8 kk steps against resident W
            #pragma unroll
            for (int kk = 0; kk < 8; kk++) {
                const uint32_t subA = (uint32_t)((kk >> 2) * 16384);
                const uint32_t subB = (uint32_t)((kc * 2 + (kk >> 2)) * 32768);
                const uint32_t kof  = (uint32_t)((kk & 3) * 32);
                const uint32_t aB = curA + subA + (uint32_t)(a_mrow * 128)
                                    + ((kof + a_khalf) ^ swx);
                const uint32_t bB = smb + SM_W + subB + (uint32_t)(b_nrow * 128)
                                    + ((kof + b_khalf) ^ swx);

                uint32_t ah[2][4];
                ldm_x4(aB,        ah[0][0], ah[0][1], ah[0][2], ah[0][3]);
                ldm_x4(aB + 2048, ah[1][0], ah[1][1], ah[1][2], ah[1][3]);

                uint32_t bh[2][4];
                ldm_x4(bB, bh[0][0], bh[0][1], bh[0][2], bh[0][3]);

                #pragma unroll
                for (int ng = 0; ng < 4; ng++) {
                    const int cb = ng & 1;
                    if (ng < 3) {
                        const int nb = cb ^ 1;
                        ldm_x4(bB + (uint32_t)((ng + 1) * 2048),
                               bh[nb][0], bh[nb][1], bh[nb][2], bh[nb][3]);
                    }
                    mma16816(acc[0][2 * ng + 0], ah[0], bh[cb][0], bh[cb][1]);
                    mma16816(acc[0][2 * ng + 1], ah[0], bh[cb][2], bh[cb][3]);
                    mma16816(acc[1][2 * ng + 0], ah[1], bh[cb][0], bh[cb][1]);
                    mma16816(acc[1][2 * ng + 1], ah[1], bh[cb][2], bh[cb][3]);
                }

                if (pre && kk == 3) {       // convert batch 1 (3 kk of cover)
                    conv_store(xv[0], nab, xr,      xc);
                    conv_store(xv[1], nab, xr + 32, xc);
                    conv_store(xv[2], nab, xr + 64, xc);
                    conv_store(xv[3], nab, xr + 96, xc);
                }
                if (pre && kk == 4) {       // LDG batch 2 (3 kk of cover)
                    #pragma unroll
                    for (int it = 0; it < 4; it++)
                        xv[it] = *(const float4*)(Xn + (size_t)(xr + it * 32) * KDIM
                                                  + kof0 + 64 + xc * 4);
                }
            }

            if (pre) {                      // convert batch 2, then barrier
                conv_store(xv[0], nab + 16384, xr,      xc);
                conv_store(xv[1], nab + 16384, xr + 32, xc);
                conv_store(xv[2], nab + 16384, xr + 64, xc);
                conv_store(xv[3], nab + 16384, xr + 96, xc);
            }
            __syncthreads();
            buf ^= 1;
        }

        // ---- epilogue for tile m: bias + relu, then reset acc
        const int mbase = m * BM + wm * 32 + (lane >> 2);
        const int nbase = wn * 64 + (lane & 3) * 2;
        #pragma unroll
        for (int mb = 0; mb < 2; mb++) {
            #pragma unroll
            for (int nb = 0; nb < 8; nb++) {
                const int n = nbase + nb * 8;
                const float b0 = sb[n], b1 = sb[n + 1];
                const int m0 = mbase + mb * 16;
                float2 v0, v1;
                v0.x = fmaxf(acc[mb][nb][0] + b0, 0.0f);
                v0.y = fmaxf(acc[mb][nb][1] + b1, 0.0f);
                v1.x = fmaxf(acc[mb][nb][2] + b0, 0.0f);
                v1.y = fmaxf(acc[mb][nb][3] + b1, 0.0f);
                *(float2*)(out + (size_t)m0 * NDIM + n) = v0;
                *(float2*)(out + (size_t)(m0 + 8) * NDIM + n) = v1;
                acc[mb][nb][0] = 0.0f; acc[mb][nb][1] = 0.0f;
                acc[mb][nb][2] = 0.0f; acc[mb][nb][3] = 0.0f;
            }
        }
    }
}

extern "C" void kernel_launch(void* const* d_in, const int* in_sizes, int n_in,
                              void* d_out, int out_size) {
    const float* X    = (const float*)d_in[0];
    const float* W    = (const float*)d_in[1];
    const float* bias = (const float*)d_in[2];
    float* out = (float*)d_out;

    cudaFuncSetAttribute(gemm_hmma_kernel,
                         cudaFuncAttributeMaxDynamicSharedMemorySize, SMEM_TOTAL);

    split_w_kernel<<<(NDIM * KDIM) / 256, 256>>>(W);

    const int ntile = in_sizes[0] / KDIM / BM;   // 1024
    gemm_hmma_kernel<<<GRID, NTHR, SMEM_TOTAL>>>(X, bias, out, ntile);
}

// round 16
// speedup vs baseline: 1.5528x; 1.0385x over previous
#include <cuda_runtime.h>
#include <cuda_fp16.h>
#include <cstdint>

// relu(X[131072,256] @ W[256,256]^T + b), fp32.
// R15: R14 persistent kernel +
//  (1) W fp32->fp16 conversion folded into the prologue (no split_w launch)
//  (2) last-chunk barrier moved AFTER the epilogue so epilogue STGs overlap
//      other warps' MMA tail.

#define KDIM 256
#define NDIM 256
#define BM   128
#define NTHR 512
#define GRID 148

#define SM_BIAS  0
#define SM_W     1024                    // 4 subs of [256 x 128B] = 128KB
#define SM_A     (1024 + 131072)         // 2 bufs x (2 subs of [128 x 128B]) = 64KB
#define SMEM_TOTAL (SM_A + 65536)        // 197632

__device__ __forceinline__ uint32_t smem_u32(const void* p) {
    uint32_t a;
    asm("{ .reg .u64 t; cvta.to.shared.u64 t, %1; cvt.u32.u64 %0, t; }" : "=r"(a) : "l"(p));
    return a;
}

__device__ __forceinline__ void ldm_x4(uint32_t addr, uint32_t& r0, uint32_t& r1,
                                       uint32_t& r2, uint32_t& r3) {
    asm volatile("ldmatrix.sync.aligned.m8n8.x4.shared.b16 {%0,%1,%2,%3}, [%4];"
                 : "=r"(r0), "=r"(r1), "=r"(r2), "=r"(r3) : "r"(addr));
}

__device__ __forceinline__ void mma16816(float* c, const uint32_t* a, uint32_t b0, uint32_t b1) {
    asm volatile(
        "mma.sync.aligned.m16n8k16.row.col.f32.f16.f16.f32 "
        "{%0,%1,%2,%3}, {%4,%5,%6,%7}, {%8,%9}, {%0,%1,%2,%3};"
        : "+f"(c[0]), "+f"(c[1]), "+f"(c[2]), "+f"(c[3])
        : "r"(a[0]), "r"(a[1]), "r"(a[2]), "r"(a[3]), "r"(b0), "r"(b1));
}

// convert one float4 (4 K values) -> fp16 and store swizzled into 128B-row tile
__device__ __forceinline__ void conv_store(float4 v, char* tile, int row, int c) {
    __half h0 = __float2half_rn(v.x);
    __half h1 = __float2half_rn(v.y);
    __half h2 = __float2half_rn(v.z);
    __half h3 = __float2half_rn(v.w);
    uint2 hv;
    hv.x = (uint32_t)__half_as_ushort(h0) | ((uint32_t)__half_as_ushort(h1) << 16);
    hv.y = (uint32_t)__half_as_ushort(h2) | ((uint32_t)__half_as_ushort(h3) << 16);
    uint32_t off = (uint32_t)(row * 128 + c * 8);
    uint32_t swo = off ^ ((off >> 3) & 0x70);
    *(uint2*)(tile + swo) = hv;
}

__global__ __launch_bounds__(NTHR, 1)
void gemm_hmma_kernel(const float* __restrict__ X,
                      const float* __restrict__ W,
                      const float* __restrict__ bias,
                      float* __restrict__ out,
                      int ntile) {
    extern __shared__ char sm[];
    const uint32_t smb = smem_u32(sm);
    const int tid  = threadIdx.x;
    const int wid  = tid >> 5;
    const int lane = tid & 31;
    const int bx   = blockIdx.x;

    const int wm = wid & 3;        // M quarter (32 rows)
    const int wn = wid >> 2;       // N quarter (64 cols)

    if (tid < 256) ((float*)(sm + SM_BIAS))[tid] = bias[tid];

    const uint32_t swx     = (uint32_t)(lane & 7) << 4;
    const int a_mrow       = wm * 32 + (lane & 7) + ((lane >> 3) & 1) * 8;
    const uint32_t a_khalf = (uint32_t)(lane >> 4) * 16;
    const int b_nrow       = wn * 64 + (lane & 7) + ((lane >> 4) ? 8 : 0);
    const uint32_t b_khalf = (uint32_t)((lane >> 3) & 1) * 16;

    const int xr = tid >> 4;       // 0..31; rows xr + 32*it
    const int xc = tid & 15;       // float4 slot within 64-K half

    float acc[2][8][4];
    #pragma unroll
    for (int i = 0; i < 2; i++)
        #pragma unroll
        for (int j = 0; j < 8; j++)
            #pragma unroll
            for (int q = 0; q < 4; q++) acc[i][j][q] = 0.0f;

    // ---- prologue (once): W fp32 -> fp16 -> smem (swizzled, 4 K-subs);
    //      X(tile bx, chunk 0) -> A buf0.
    #pragma unroll
    for (int it = 0; it < 16; it++) {
        int id = tid + it * NTHR;          // 0..8191 : 16B fp16 units of W
        int r  = id >> 5;                  // W row 0..255
        int ks = id & 31;                  // 16B unit within row (8 fp16)
        int kch = ks >> 3, c = ks & 7;
        const float4* wp = (const float4*)(W + r * KDIM + ks * 8);
        float4 w0 = wp[0];
        float4 w1 = wp[1];
        __half h0 = __float2half_rn(w0.x), h1 = __float2half_rn(w0.y);
        __half h2 = __float2half_rn(w0.z), h3 = __float2half_rn(w0.w);
        __half h4 = __float2half_rn(w1.x), h5 = __float2half_rn(w1.y);
        __half h6 = __float2half_rn(w1.z), h7 = __float2half_rn(w1.w);
        uint4 hv;
        hv.x = (uint32_t)__half_as_ushort(h0) | ((uint32_t)__half_as_ushort(h1) << 16);
        hv.y = (uint32_t)__half_as_ushort(h2) | ((uint32_t)__half_as_ushort(h3) << 16);
        hv.z = (uint32_t)__half_as_ushort(h4) | ((uint32_t)__half_as_ushort(h5) << 16);
        hv.w = (uint32_t)__half_as_ushort(h6) | ((uint32_t)__half_as_ushort(h7) << 16);
        uint32_t off = (uint32_t)(r * 128 + c * 16);
        uint32_t swo = off ^ ((off >> 3) & 0x70);
        *(uint4*)(sm + SM_W + kch * 32768 + swo) = hv;
    }
    {
        const float* Xb = X + (size_t)bx * BM * KDIM;
        char* ab = sm + SM_A;
        #pragma unroll
        for (int it = 0; it < 4; it++) {
            float4 v = *(const float4*)(Xb + (size_t)(xr + it * 32) * KDIM + xc * 4);
            conv_store(v, ab, xr + it * 32, xc);                   // K 0..63 -> sub0
        }
        #pragma unroll
        for (int it = 0; it < 4; it++) {
            float4 v = *(const float4*)(Xb + (size_t)(xr + it * 32) * KDIM + 64 + xc * 4);
            conv_store(v, ab + 16384, xr + it * 32, xc);           // K 64..127 -> sub1
        }
    }
    __syncthreads();

    int buf = 0;
    const float* sb = (const float*)(sm + SM_BIAS);

    for (int m = bx; m < ntile; m += GRID) {
        const float* Xb = X + (size_t)m * BM * KDIM;

        #pragma unroll
        for (int kc = 0; kc < 2; kc++) {
            const uint32_t curA = smb + SM_A + (uint32_t)(buf * 32768);
            char* nab = sm + SM_A + ((buf ^ 1) * 32768);
            const bool pre = (kc == 0) || (m + GRID < ntile);
            const float* Xn = (kc == 0) ? Xb : X + (size_t)(m + GRID) * BM * KDIM;
            const int kof0 = (kc == 0) ? 128 : 0;

            float4 xv[4];

            // prefetch batch 1 of next chunk's X (full-chunk LDG cover)
            if (pre) {
                #pragma unroll
                for (int it = 0; it < 4; it++)
                    xv[it] = *(const float4*)(Xn + (size_t)(xr + it * 32) * KDIM + kof0 + xc * 4);
            }

            // ---- MMA loop: 8 kk steps against resident W
            #pragma unroll
            for (int kk = 0; kk < 8; kk++) {
                const uint32_t subA = (uint32_t)((kk >> 2) * 16384);
                const uint32_t subB = (uint32_t)((kc * 2 + (kk >> 2)) * 32768);
                const uint32_t kof  = (uint32_t)((kk & 3) * 32);
                const uint32_t aB = curA + subA + (uint32_t)(a_mrow * 128)
                                    + ((kof + a_khalf) ^ swx);
                const uint32_t bB = smb + SM_W + subB + (uint32_t)(b_nrow * 128)
                                    + ((kof + b_khalf) ^ swx);

                uint32_t ah[2][4];
                ldm_x4(aB,        ah[0][0], ah[0][1], ah[0][2], ah[0][3]);
                ldm_x4(aB + 2048, ah[1][0], ah[1][1], ah[1][2], ah[1][3]);

                uint32_t bh[2][4];
                ldm_x4(bB, bh[0][0], bh[0][1], bh[0][2], bh[0][3]);

                #pragma unroll
                for (int ng = 0; ng < 4; ng++) {
                    const int cb = ng & 1;
                    if (ng < 3) {
                        const int nb = cb ^ 1;
                        ldm_x4(bB + (uint32_t)((ng + 1) * 2048),
                               bh[nb][0], bh[nb][1], bh[nb][2], bh[nb][3]);
                    }
                    mma16816(acc[0][2 * ng + 0], ah[0], bh[cb][0], bh[cb][1]);
                    mma16816(acc[0][2 * ng + 1], ah[0], bh[cb][2], bh[cb][3]);
                    mma16816(acc[1][2 * ng + 0], ah[1], bh[cb][0], bh[cb][1]);
                    mma16816(acc[1][2 * ng + 1], ah[1], bh[cb][2], bh[cb][3]);
                }

                if (pre && kk == 3) {       // convert batch 1 (3 kk of cover)
                    conv_store(xv[0], nab, xr,      xc);
                    conv_store(xv[1], nab, xr + 32, xc);
                    conv_store(xv[2], nab, xr + 64, xc);
                    conv_store(xv[3], nab, xr + 96, xc);
                }
                if (pre && kk == 4) {       // LDG batch 2 (3 kk of cover)
                    #pragma unroll
                    for (int it = 0; it < 4; it++)
                        xv[it] = *(const float4*)(Xn + (size_t)(xr + it * 32) * KDIM
                                                  + kof0 + 64 + xc * 4);
                }
            }

            if (pre) {                      // convert batch 2
                conv_store(xv[0], nab + 16384, xr,      xc);
                conv_store(xv[1], nab + 16384, xr + 32, xc);
                conv_store(xv[2], nab + 16384, xr + 64, xc);
                conv_store(xv[3], nab + 16384, xr + 96, xc);
            }
            // kc0: barrier here (A buf handoff). kc1: barrier DEFERRED until
            // after the epilogue so epilogue STGs overlap other warps' MMAs.
            if (kc == 0) __syncthreads();
            buf ^= 1;
        }

        // ---- epilogue for tile m (no barrier before it): bias + relu
        const int mbase = m * BM + wm * 32 + (lane >> 2);
        const int nbase = wn * 64 + (lane & 3) * 2;
        #pragma unroll
        for (int mb = 0; mb < 2; mb++) {
            #pragma unroll
            for (int nb = 0; nb < 8; nb++) {
                const int n = nbase + nb * 8;
                const float b0 = sb[n], b1 = sb[n + 1];
                const int m0 = mbase + mb * 16;
                float2 v0, v1;
                v0.x = fmaxf(acc[mb][nb][0] + b0, 0.0f);
                v0.y = fmaxf(acc[mb][nb][1] + b1, 0.0f);
                v1.x = fmaxf(acc[mb][nb][2] + b0, 0.0f);
                v1.y = fmaxf(acc[mb][nb][3] + b1, 0.0f);
                *(float2*)(out + (size_t)m0 * NDIM + n) = v0;
                *(float2*)(out + (size_t)(m0 + 8) * NDIM + n) = v1;
                acc[mb][nb][0] = 0.0f; acc[mb][nb][1] = 0.0f;
                acc[mb][nb][2] = 0.0f; acc[mb][nb][3] = 0.0f;
            }
        }

        // deferred barrier: next-tile A buffer (written during kc1) is now
        // guaranteed complete across the CTA before anyone MMAs from it.
        __syncthreads();
    }
}

extern "C" void kernel_launch(void* const* d_in, const int* in_sizes, int n_in,
                              void* d_out, int out_size) {
    const float* X    = (const float*)d_in[0];
    const float* W    = (const float*)d_in[1];
    const float* bias = (const float*)d_in[2];
    float* out = (float*)d_out;

    cudaFuncSetAttribute(gemm_hmma_kernel,
                         cudaFuncAttributeMaxDynamicSharedMemorySize, SMEM_TOTAL);

    const int ntile = in_sizes[0] / KDIM / BM;   // 1024
    gemm_hmma_kernel<<<GRID, NTHR, SMEM_TOTAL>>>(X, W, bias, out, ntile);
}